// round 12
// baseline (speedup 1.0000x reference)
#include <cuda_runtime.h>
#include <math_constants.h>

// Problem constants
#define NND   50000
#define EED   800000
#define DDIM  128
#define HH    8
#define CCH   16
#define LLAY  4
#define QKVS  512   // 4*128 packed output columns: [q|k|v|skip]

typedef unsigned int u32;

// ---------------- scratch (device globals; no allocation allowed) ----------
__device__ __align__(16) float g_x[NND * DDIM];          // node features between layers
__device__ __align__(16) float g_qkvs[NND * QKVS];       // [q|k|v|skip] per node
__device__ __align__(16) float g_sp[EED * HH];           // per-edge raw scores (CSR order)
__device__ __align__(16) float g_Wp[LLAY * DDIM * QKVS]; // packed weights
__device__ __align__(16) float g_bp[LLAY * QKVS];        // packed biases
// CSR build
__device__ int g_deg[NND];
__device__ int g_off[NND + 1];
__device__ int g_cur[NND];
__device__ int g_part[256];
__device__ int g_csr_src[EED];

// ---------------- weight packing -------------------------------------------
__global__ void pack_w(const float* __restrict__ Wq, const float* __restrict__ Wk,
                       const float* __restrict__ Wv, const float* __restrict__ Ws,
                       const float* __restrict__ bq, const float* __restrict__ bk,
                       const float* __restrict__ bv, const float* __restrict__ bs) {
    int i = blockIdx.x * blockDim.x + threadIdx.x;
    if (i < LLAY * DDIM * QKVS) {
        int l = i >> 16;          // 128*512 = 65536
        int k = (i >> 9) & 127;
        int j = i & 511;
        int which = j >> 7, jj = j & 127;
        const float* W = (which == 0) ? Wq : (which == 1) ? Wk : (which == 2) ? Wv : Ws;
        g_Wp[i] = W[l * (DDIM * DDIM) + k * DDIM + jj];
    }
    if (i < LLAY * QKVS) {
        int l = i >> 9, j = i & 511;
        int which = j >> 7, jj = j & 127;
        const float* b = (which == 0) ? bq : (which == 1) ? bk : (which == 2) ? bv : bs;
        g_bp[i] = b[l * DDIM + jj];
    }
}

// ---------------- CSR build --------------------------------------------------
__global__ void deg_zero_k() {
    int i = blockIdx.x * blockDim.x + threadIdx.x;
    if (i < NND) g_deg[i] = 0;
}

__global__ void hist_k(const int* __restrict__ ei) {
    int e = blockIdx.x * blockDim.x + threadIdx.x;
    if (e < EED) atomicAdd(&g_deg[ei[EED + e]], 1);
}

__global__ void scan1_k() {
    __shared__ int s[256];
    int t = threadIdx.x;
    int i = blockIdx.x * 256 + t;
    int v = (i < NND) ? g_deg[i] : 0;
    s[t] = v;
    __syncthreads();
#pragma unroll
    for (int off = 1; off < 256; off <<= 1) {
        int x = (t >= off) ? s[t - off] : 0;
        __syncthreads();
        s[t] += x;
        __syncthreads();
    }
    if (i < NND) g_off[i] = s[t] - v;     // exclusive within block
    if (t == 255) g_part[blockIdx.x] = s[255];
}

__global__ void scan2_k(int nblk) {
    __shared__ int s[256];
    int t = threadIdx.x;
    int v = (t < nblk) ? g_part[t] : 0;
    s[t] = v;
    __syncthreads();
#pragma unroll
    for (int off = 1; off < 256; off <<= 1) {
        int x = (t >= off) ? s[t - off] : 0;
        __syncthreads();
        s[t] += x;
        __syncthreads();
    }
    if (t < nblk) g_part[t] = s[t] - v;
}

__global__ void scan3_k() {
    int i = blockIdx.x * blockDim.x + threadIdx.x;
    if (i < NND) {
        int o = g_off[i] + g_part[i >> 8];
        g_off[i] = o;
        g_cur[i] = o;
    }
    if (i == 0) g_off[NND] = EED;
}

__global__ void scatter_k(const int* __restrict__ ei) {
    int e = blockIdx.x * blockDim.x + threadIdx.x;
    if (e >= EED) return;
    int dst = ei[EED + e];
    int pos = atomicAdd(&g_cur[dst], 1);
    g_csr_src[pos] = ei[e];
}

// ---------------- tf32x3 tensor-core GEMM -----------------------------------
// C[M,Ncols] = A[M,128] @ B[128,Ncols] + bias, near-fp32 precision:
// x = hi + lo (hi = tf32(x), lo = tf32(x-hi));  A*B ~= Ah*Bh + Ah*Bl + Al*Bh.
// Block tile 128x128, 8 warps, warp tile 64x32, mma.sync.m16n8k8, K staged 16.
__device__ __forceinline__ u32 f2tf32(float f) {
    u32 r;
    asm("cvt.rna.tf32.f32 %0, %1;" : "=r"(r) : "f"(f));
    return r;
}
__device__ __forceinline__ void split_tf32(float v, u32& h, u32& l) {
    h = f2tf32(v);
    l = f2tf32(v - __uint_as_float(h));
}

#define MMA_TF32(ACC, AF, BF)                                                   \
    asm volatile(                                                               \
        "mma.sync.aligned.m16n8k8.row.col.f32.tf32.tf32.f32 "                   \
        "{%0,%1,%2,%3}, {%4,%5,%6,%7}, {%8,%9}, {%0,%1,%2,%3};"                 \
        : "+f"((ACC)[0]), "+f"((ACC)[1]), "+f"((ACC)[2]), "+f"((ACC)[3])        \
        : "r"((AF)[0]), "r"((AF)[1]), "r"((AF)[2]), "r"((AF)[3]),               \
          "r"((BF)[0]), "r"((BF)[1]))

__device__ __forceinline__ void gemm_body(const float* __restrict__ A,
                                          const float* __restrict__ B,
                                          const float* __restrict__ bias,
                                          float* __restrict__ Cmat,
                                          int M, int Ncols) {
    __shared__ u32 sAh[128][20];   // [m][k] pad 20: banks 20*lq+lr all-distinct
    __shared__ u32 sAl[128][20];
    __shared__ u32 sBh[16][136];   // [k][n] pad 136: banks 8*lr+lq all-distinct
    __shared__ u32 sBl[16][136];
    const int tid = threadIdx.x;
    const int warpId = tid >> 5, lane = tid & 31;
    const int wm = warpId & 1;          // 2 warps along M (64 rows each)
    const int wn = warpId >> 1;         // 4 warps along N (32 cols each)
    const int lq = lane >> 2;           // 0..7
    const int lr = lane & 3;            // 0..3
    const int rowBase = blockIdx.y * 128;
    const int colBase = blockIdx.x * 128;

    float acc[4][4][4];                 // [mfrag][nfrag][creg]
#pragma unroll
    for (int i = 0; i < 4; i++)
#pragma unroll
        for (int j = 0; j < 4; j++)
#pragma unroll
            for (int c = 0; c < 4; c++) acc[i][j][c] = 0.0f;

    for (int kk = 0; kk < 128; kk += 16) {
        // A stage: 128 rows x 16 k = 512 float4; 2 per thread, hi/lo split
#pragma unroll
        for (int t = 0; t < 2; t++) {
            int idx4 = tid + t * 256;
            int m = idx4 >> 2, kq = idx4 & 3;
            int row = rowBase + m;
            float4 a = (row < M) ? *(const float4*)&A[row * 128 + kk + kq * 4]
                                 : make_float4(0.f, 0.f, 0.f, 0.f);
            split_tf32(a.x, sAh[m][kq * 4 + 0], sAl[m][kq * 4 + 0]);
            split_tf32(a.y, sAh[m][kq * 4 + 1], sAl[m][kq * 4 + 1]);
            split_tf32(a.z, sAh[m][kq * 4 + 2], sAl[m][kq * 4 + 2]);
            split_tf32(a.w, sAh[m][kq * 4 + 3], sAl[m][kq * 4 + 3]);
        }
        // B stage: 16 k x 128 cols = 512 float4; 2 per thread, hi/lo split
#pragma unroll
        for (int t = 0; t < 2; t++) {
            int idx4 = tid + t * 256;
            int k = idx4 >> 5, n4 = idx4 & 31;
            float4 b = *(const float4*)&B[(kk + k) * Ncols + colBase + n4 * 4];
            split_tf32(b.x, sBh[k][n4 * 4 + 0], sBl[k][n4 * 4 + 0]);
            split_tf32(b.y, sBh[k][n4 * 4 + 1], sBl[k][n4 * 4 + 1]);
            split_tf32(b.z, sBh[k][n4 * 4 + 2], sBl[k][n4 * 4 + 2]);
            split_tf32(b.w, sBh[k][n4 * 4 + 3], sBl[k][n4 * 4 + 3]);
        }
        __syncthreads();

#pragma unroll
        for (int ks = 0; ks < 2; ks++) {
            const int k0 = ks * 8;
            u32 afh[4][4], afl[4][4];
#pragma unroll
            for (int mf = 0; mf < 4; mf++) {
                int r = wm * 64 + mf * 16 + lq;
                afh[mf][0] = sAh[r][k0 + lr];
                afh[mf][1] = sAh[r + 8][k0 + lr];
                afh[mf][2] = sAh[r][k0 + lr + 4];
                afh[mf][3] = sAh[r + 8][k0 + lr + 4];
                afl[mf][0] = sAl[r][k0 + lr];
                afl[mf][1] = sAl[r + 8][k0 + lr];
                afl[mf][2] = sAl[r][k0 + lr + 4];
                afl[mf][3] = sAl[r + 8][k0 + lr + 4];
            }
            u32 bfh[4][2], bfl[4][2];
#pragma unroll
            for (int nf = 0; nf < 4; nf++) {
                int col = wn * 32 + nf * 8 + lq;
                bfh[nf][0] = sBh[k0 + lr][col];
                bfh[nf][1] = sBh[k0 + lr + 4][col];
                bfl[nf][0] = sBl[k0 + lr][col];
                bfl[nf][1] = sBl[k0 + lr + 4][col];
            }
#pragma unroll
            for (int mf = 0; mf < 4; mf++)
#pragma unroll
                for (int nf = 0; nf < 4; nf++) {
                    MMA_TF32(acc[mf][nf], afl[mf], bfh[nf]);  // lo*hi
                    MMA_TF32(acc[mf][nf], afh[mf], bfl[nf]);  // hi*lo
                    MMA_TF32(acc[mf][nf], afh[mf], bfh[nf]);  // hi*hi last (largest)
                }
        }
        __syncthreads();
    }

    // epilogue: c0,c1 -> (row, col..col+1); c2,c3 -> (row+8, ...)
#pragma unroll
    for (int mf = 0; mf < 4; mf++) {
        int row0 = rowBase + wm * 64 + mf * 16 + lq;
#pragma unroll
        for (int nf = 0; nf < 4; nf++) {
            int col = colBase + wn * 32 + nf * 8 + 2 * lr;
            float2 b2 = *(const float2*)&bias[col];
            if (row0 < M) {
                float2 o = make_float2(acc[mf][nf][0] + b2.x, acc[mf][nf][1] + b2.y);
                *(float2*)&Cmat[row0 * Ncols + col] = o;
            }
            if (row0 + 8 < M) {
                float2 o = make_float2(acc[mf][nf][2] + b2.x, acc[mf][nf][3] + b2.y);
                *(float2*)&Cmat[(row0 + 8) * Ncols + col] = o;
            }
        }
    }
}

__global__ void __launch_bounds__(256, 1) gemm_qkvs(const float* __restrict__ x_ext,
                                                    int layer, int use_ext) {
    const float* A = use_ext ? x_ext : g_x;
    gemm_body(A, &g_Wp[layer * DDIM * QKVS], &g_bp[layer * QKVS], g_qkvs, NND, QKVS);
}

__global__ void __launch_bounds__(256, 1) gemm_out(const float* __restrict__ Wout,
                                                   const float* __restrict__ bout,
                                                   float* __restrict__ out) {
    gemm_body(g_x, Wout, bout, out, NND, DDIM);
}

// ---------------- fused attention: warp per dst node, no atomics -------------
// lane layout: h = lane>>2 (head), pl = lane&3; output col block = lane*4
__global__ void attn_fused_k() {
    int gw = (blockIdx.x * blockDim.x + threadIdx.x) >> 5;
    if (gw >= NND) return;
    int lane = threadIdx.x & 31;
    int h = lane >> 2, pl = lane & 3;
    int beg = g_off[gw], end = g_off[gw + 1];

    // ---- pass 1: scores + max ----
    float4 q4 = *(const float4*)&g_qkvs[gw * QKVS + h * CCH + pl * 4];
    float m = -CUDART_INF_F;
    for (int i = beg; i < end; i++) {
        int src = g_csr_src[i];
        float4 k4 = *(const float4*)&g_qkvs[src * QKVS + 128 + h * CCH + pl * 4];
        float s = q4.x * k4.x + q4.y * k4.y + q4.z * k4.z + q4.w * k4.w;
        s += __shfl_xor_sync(0xFFFFFFFFu, s, 1);
        s += __shfl_xor_sync(0xFFFFFFFFu, s, 2);
        s *= 0.25f;                       // 1/sqrt(16)
        if (pl == 0) g_sp[i * 8 + h] = s;
        m = fmaxf(m, s);
    }

    // ---- pass 2: exp, z, and p*v accumulation (registers only) ----
    float z = 0.0f;
    float4 acc = make_float4(0.f, 0.f, 0.f, 0.f);
    for (int i = beg; i < end; i++) {
        int src = g_csr_src[i];
        float p = __expf(g_sp[i * 8 + h] - m);
        z += p;
        float4 v4 = *(const float4*)&g_qkvs[src * QKVS + 256 + lane * 4];
        acc.x += p * v4.x;
        acc.y += p * v4.y;
        acc.z += p * v4.z;
        acc.w += p * v4.w;
    }
    float invz = (beg < end) ? (1.0f / z) : 0.0f;

    // ---- normalize + skip + ReLU ----
    float4 sk = *(const float4*)&g_qkvs[gw * QKVS + 384 + lane * 4];
    float4 o;
    o.x = fmaxf(acc.x * invz + sk.x, 0.f);
    o.y = fmaxf(acc.y * invz + sk.y, 0.f);
    o.z = fmaxf(acc.z * invz + sk.z, 0.f);
    o.w = fmaxf(acc.w * invz + sk.w, 0.f);
    *(float4*)&g_x[gw * DDIM + lane * 4] = o;
}

// ---------------- launch -----------------------------------------------------
extern "C" void kernel_launch(void* const* d_in, const int* in_sizes, int n_in,
                              void* d_out, int out_size) {
    const float* x    = (const float*)d_in[0];
    const int*   ei   = (const int*)d_in[1];
    // d_in[2] = batch (unused: single graph)
    const float* Wq   = (const float*)d_in[3];
    const float* bq   = (const float*)d_in[4];
    const float* Wk   = (const float*)d_in[5];
    const float* bk   = (const float*)d_in[6];
    const float* Wv   = (const float*)d_in[7];
    const float* bv   = (const float*)d_in[8];
    const float* Ws   = (const float*)d_in[9];
    const float* bs   = (const float*)d_in[10];
    const float* Wout = (const float*)d_in[11];
    const float* bout = (const float*)d_in[12];
    float* out = (float*)d_out;

    const int TPB = 256;
    const int nScanBlk = (NND + 255) / 256;            // 196
    const int nEdgeBlk = (EED + TPB - 1) / TPB;
    const int nWarpBlk = (NND + 7) / 8;                // 8 warps/block, warp per node
    dim3 gemmGridQKVS(QKVS / 128, (NND + 127) / 128);  // (4, 391)
    dim3 gemmGridOut(DDIM / 128, (NND + 127) / 128);   // (1, 391)

    // one-time (per launch) prep
    pack_w<<<(LLAY * DDIM * QKVS + TPB - 1) / TPB, TPB>>>(Wq, Wk, Wv, Ws, bq, bk, bv, bs);
    deg_zero_k<<<(NND + TPB - 1) / TPB, TPB>>>();
    hist_k<<<nEdgeBlk, TPB>>>(ei);
    scan1_k<<<nScanBlk, 256>>>();
    scan2_k<<<1, 256>>>(nScanBlk);
    scan3_k<<<(NND + TPB - 1) / TPB, TPB>>>();
    scatter_k<<<nEdgeBlk, TPB>>>(ei);

    for (int l = 0; l < LLAY; l++) {
        gemm_qkvs<<<gemmGridQKVS, 256>>>(x, l, l == 0 ? 1 : 0);
        attn_fused_k<<<nWarpBlk, TPB>>>();
    }

    gemm_out<<<gemmGridOut, 256>>>(Wout, bout, out);
}